// round 8
// baseline (speedup 1.0000x reference)
#include <cuda_runtime.h>
#include <stdint.h>

#define NSLOTS 4096
#define TPB 512
#define PT 8            // NSLOTS / TPB
#define NW (TPB / 32)   // 16 warps
#define NBINS 4096
#define KPAD 672
#define EPSF 1e-3f

__global__ __launch_bounds__(TPB) void latent_handler_kernel(
    const float* __restrict__ z_where,
    const float* __restrict__ z_present,
    const float* __restrict__ z_what_loc,
    const float* __restrict__ z_depth_loc,
    const float* __restrict__ neg_priority,
    float* __restrict__ out,
    int B, int K)
{
    __shared__ unsigned int s_keys[NSLOTS];   // 16KB
    __shared__ int s_hist[NBINS];             // 16KB (reused as candidate list)
    __shared__ int s_idxmap[KPAD];            // packed: slot | (present << 15)
    __shared__ int s_wsum[NW];
    __shared__ int s_scal[8];

    const int b    = blockIdx.x >> 1;         // row
    const int half = blockIdx.x & 1;          // which half of epilogue
    const int tid  = threadIdx.x;
    const int lane = tid & 31;
    const int warp = tid >> 5;
    const int base = tid * PT;

    // ================= selection (duplicated across the 2 row-CTAs) =================
    unsigned int presmask = 0;                 // bit j: slot base+j present
    int digr[PT];
    {
        const float4* zp4 = (const float4*)(z_present    + (size_t)b * NSLOTS);
        const float4* np4 = (const float4*)(neg_priority + (size_t)b * NSLOTS);
        #pragma unroll
        for (int v = 0; v < 2; v++) {
            float4 p = zp4[tid * 2 + v];
            float4 q = np4[tid * 2 + v];
            float pv[4] = {p.x, p.y, p.z, p.w};
            float qv[4] = {q.x, q.y, q.z, q.w};
            #pragma unroll
            for (int u = 0; u < 4; u++) {
                int j = v * 4 + u;
                bool pres = pv[u] > EPSF;
                if (pres) presmask |= (1u << j);
                unsigned int bits = __float_as_uint(qv[u]);
                unsigned int msk  = (unsigned int)(((int)bits) >> 31) | 0x80000000u;
                s_keys[base + j] = pres ? 0xFFFFFFFFu : (bits ^ msk);
                int d = __float2int_rd(qv[u] * 4096.0f);   // exact ×2^12, monotone
                digr[j] = min(NBINS - 1, max(0, d));
            }
        }
    }
    // zero histogram: 4096 ints / 512 threads = 2 int4 per thread
    ((int4*)s_hist)[tid]       = make_int4(0, 0, 0, 0);
    ((int4*)s_hist)[tid + TPB] = make_int4(0, 0, 0, 0);
    int sum = __popc(presmask);
    int ws = sum;
    #pragma unroll
    for (int o = 1; o < 32; o <<= 1) {
        int v = __shfl_up_sync(0xFFFFFFFFu, ws, o);
        if (lane >= o) ws += v;
    }
    if (lane == 31) s_wsum[warp] = ws;
    if (tid == 0) { s_scal[1] = -1; s_scal[4] = 0; }
    __syncthreads();                                    // B1

    if (warp == 0 && lane < NW) {                       // n_present total
        int v = s_wsum[lane];
        #pragma unroll
        for (int o = NW / 2; o; o >>= 1) v += __shfl_down_sync(0xFFFFu, v, o);
        if (lane == 0) s_scal[0] = v;
    }
    #pragma unroll
    for (int j = 0; j < PT; j++)
        if (!((presmask >> j) & 1)) atomicAdd(&s_hist[digr[j]], 1);
    __syncthreads();                                    // B2

    const int n_present = s_scal[0];
    const int n_neg = K - n_present;

    // winner-bin search: block scan over 4096 bins (8 bins/thread)
    int4 c0 = ((int4*)s_hist)[tid * 2];
    int4 c1 = ((int4*)s_hist)[tid * 2 + 1];
    int cb[8] = {c0.x, c0.y, c0.z, c0.w, c1.x, c1.y, c1.z, c1.w};
    int tot = 0;
    #pragma unroll
    for (int j = 0; j < 8; j++) tot += cb[j];
    int sc = tot;
    #pragma unroll
    for (int o = 1; o < 32; o <<= 1) {
        int v = __shfl_up_sync(0xFFFFFFFFu, sc, o);
        if (lane >= o) sc += v;
    }
    if (lane == 31) s_wsum[warp] = sc;
    __syncthreads();                                    // B3
    if (warp == 0 && lane < NW) {
        int v = s_wsum[lane];
        int vs = v;
        #pragma unroll
        for (int o = 1; o < NW; o <<= 1) {
            int t2 = __shfl_up_sync(0xFFFFu, vs, o);
            if (lane >= o) vs += t2;
        }
        s_wsum[lane] = vs - v;
    }
    __syncthreads();                                    // B4
    if (n_neg > 0) {
        int cum = s_wsum[warp] + (sc - tot);
        #pragma unroll
        for (int j = 0; j < 8; j++) {
            if (cum < n_neg && n_neg <= cum + cb[j]) {
                s_scal[1] = tid * 8 + j;
                s_scal[2] = n_neg - cum;
                s_scal[3] = cb[j];
            }
            cum += cb[j];
        }
    }
    __syncthreads();                                    // B5
    const int winbin = s_scal[1];
    const int t_rem  = s_scal[2];
    const int cnt_eq = s_scal[3];
    const bool need_exact = (winbin >= 0) && (t_rem < cnt_eq);

    int* s_cand = s_hist;                               // reuse
    if (need_exact) {
        #pragma unroll
        for (int j = 0; j < PT; j++)
            if (!((presmask >> j) & 1) && digr[j] == winbin)
                s_cand[atomicAdd(&s_scal[4], 1)] = base + j;
        __syncthreads();                                // B6 (uniform branch)
    }

    // keep decision (bitmask) + compaction scan -> packed idxmap
    unsigned int keepmask = 0;
    #pragma unroll
    for (int j = 0; j < PT; j++) {
        bool kp;
        if ((presmask >> j) & 1) kp = true;
        else if (winbin < 0) kp = false;
        else {
            int d = digr[j];
            if (d < winbin) kp = true;
            else if (d > winbin) kp = false;
            else if (!need_exact) kp = true;
            else {
                unsigned int my = s_keys[base + j];
                int myi = base + j, r = 0, nc = s_scal[4];
                for (int t = 0; t < nc; t++) {
                    int ci = s_cand[t];
                    unsigned int ck = s_keys[ci];
                    r += (ck < my) || (ck == my && ci < myi);
                }
                kp = (r < t_rem);                       // stable (key, idx) rank
            }
        }
        if (kp) keepmask |= (1u << j);
    }
    sum = __popc(keepmask);
    ws = sum;
    #pragma unroll
    for (int o = 1; o < 32; o <<= 1) {
        int v = __shfl_up_sync(0xFFFFFFFFu, ws, o);
        if (lane >= o) ws += v;
    }
    if (lane == 31) s_wsum[warp] = ws;
    __syncthreads();                                    // B7
    if (warp == 0 && lane < NW) {
        int v = s_wsum[lane];
        int vs = v;
        #pragma unroll
        for (int o = 1; o < NW; o <<= 1) {
            int t2 = __shfl_up_sync(0xFFFFu, vs, o);
            if (lane >= o) vs += t2;
        }
        s_wsum[lane] = vs - v;
    }
    __syncthreads();                                    // B8
    {
        int tb = s_wsum[warp] + (ws - sum);
        #pragma unroll
        for (int j = 0; j < PT; j++)
            if ((keepmask >> j) & 1) {
                int p = tb + __popc(keepmask & ((1u << j) - 1));
                if (p < KPAD)
                    s_idxmap[p] = (base + j) | (((presmask >> j) & 1) << 15);
            }
    }
    __syncthreads();                                    // B9

    // ================= epilogue: this CTA handles half of K =================
    const int Kh     = (K + 1) >> 1;
    const int pstart = half * Kh;
    const int pend   = min(K, pstart + Kh);
    const int n      = pend - pstart;

    float* out_where = out;                             // [B, K, 4]
    float* out_mod   = out + (size_t)B * K * 4;         // [B, K, 1]
    float* out_what  = out + (size_t)B * K * 5;         // [B, K, 64]
    float* out_depth = out + (size_t)B * K * 69;        // [B, K, 1]

    const float4* zw4 = (const float4*)z_where + (size_t)b * NSLOTS;
    const float*  zd  = z_depth_loc + (size_t)b * NSLOTS;

    for (int t = tid; t < n; t += TPB) {
        int p = pstart + t;
        int e = s_idxmap[p];
        int slot = e & 0xFFF;
        bool pres = (e & 0x8000) != 0;
        float4 w = __ldg(&zw4[slot]);
        float m = fmaxf(w.z, w.w);
        ((float4*)out_where)[(size_t)b * K + p] = make_float4(w.x, w.y, m, m);
        out_mod[(size_t)b * K + p]   = pres ? 1.0f : -1.0f;
        out_depth[(size_t)b * K + p] = pres ? __ldg(&zd[slot]) : 0.0f;
    }

    const float4* wl4 = (const float4*)z_what_loc + (size_t)b * NSLOTS * 16;
    float4* ow4 = (float4*)out_what + ((size_t)b * K + pstart) * 16;
    const int total = n * 16;
    const int c = tid & 15;                             // loop-invariant column
    int i = tid;
    // batches of 4 for MLP
    for (; i + 3 * TPB < total; i += 4 * TPB) {
        int e0 = s_idxmap[pstart + ((i          ) >> 4)];
        int e1 = s_idxmap[pstart + ((i +     TPB) >> 4)];
        int e2 = s_idxmap[pstart + ((i + 2 * TPB) >> 4)];
        int e3 = s_idxmap[pstart + ((i + 3 * TPB) >> 4)];
        float4 v0 = make_float4(0.f, 0.f, 0.f, 0.f);
        float4 v1 = v0, v2 = v0, v3 = v0;
        if (e0 & 0x8000) v0 = __ldg(&wl4[(e0 & 0xFFF) * 16 + c]);
        if (e1 & 0x8000) v1 = __ldg(&wl4[(e1 & 0xFFF) * 16 + c]);
        if (e2 & 0x8000) v2 = __ldg(&wl4[(e2 & 0xFFF) * 16 + c]);
        if (e3 & 0x8000) v3 = __ldg(&wl4[(e3 & 0xFFF) * 16 + c]);
        ow4[i          ] = v0;
        ow4[i +     TPB] = v1;
        ow4[i + 2 * TPB] = v2;
        ow4[i + 3 * TPB] = v3;
    }
    for (; i < total; i += TPB) {
        int e = s_idxmap[pstart + (i >> 4)];
        float4 v = make_float4(0.f, 0.f, 0.f, 0.f);
        if (e & 0x8000) v = __ldg(&wl4[(e & 0xFFF) * 16 + c]);
        ow4[i] = v;
    }
}

extern "C" void kernel_launch(void* const* d_in, const int* in_sizes, int n_in,
                              void* d_out, int out_size) {
    const float* z_where      = (const float*)d_in[0];
    const float* z_present    = (const float*)d_in[1];
    const float* z_what_loc   = (const float*)d_in[2];
    // d_in[3] = z_what_scale  (never read)
    const float* z_depth_loc  = (const float*)d_in[4];
    // d_in[5] = z_depth_scale (never read)
    const float* neg_priority = (const float*)d_in[6];

    const int B = in_sizes[6] / NSLOTS;
    const int K = out_size / (B * 70);

    latent_handler_kernel<<<B * 2, TPB>>>(z_where, z_present, z_what_loc,
                                          z_depth_loc, neg_priority,
                                          (float*)d_out, B, K);
}

// round 13
// speedup vs baseline: 1.0129x; 1.0129x over previous
#include <cuda_runtime.h>
#include <stdint.h>

#define NSLOTS 4096
#define TPB 1024
#define PT 4            // NSLOTS / TPB
#define NBINS 4096
#define KPAD 672
#define NSLICE 8
#define TPB_B 128
#define EPSF 1e-3f

__device__ int g_idx[256 * KPAD];   // packed: slot | (present << 15)

// =============== Kernel A: selection + small outputs ===============
__global__ __launch_bounds__(TPB) void select_kernel(
    const float* __restrict__ z_where,
    const float* __restrict__ z_present,
    const float* __restrict__ z_depth_loc,
    const float* __restrict__ neg_priority,
    float* __restrict__ out,
    int B, int K)
{
    __shared__ unsigned int s_keys[NSLOTS];   // 16KB
    __shared__ int s_hist[NBINS];             // 16KB (reused as candidate list)
    __shared__ int s_idxmap[KPAD];
    __shared__ int s_wsum[32];
    __shared__ int s_scal[8];

    const int b    = blockIdx.x;
    const int tid  = threadIdx.x;
    const int lane = tid & 31;
    const int warp = tid >> 5;
    const int base = tid * PT;

    // ---- load presence + priority, build keys/digits ----
    int presf[PT], local[PT], digr[PT];
    int sum = 0;
    {
        float4 p = ((const float4*)(z_present    + (size_t)b * NSLOTS))[tid];
        float4 q = ((const float4*)(neg_priority + (size_t)b * NSLOTS))[tid];
        float pv[4] = {p.x, p.y, p.z, p.w};
        float qv[4] = {q.x, q.y, q.z, q.w};
        #pragma unroll
        for (int j = 0; j < PT; j++) {
            bool pres = pv[j] > EPSF;
            presf[j] = pres ? 1 : 0;
            local[j] = sum;
            sum += presf[j];
            unsigned int bits = __float_as_uint(qv[j]);
            unsigned int msk  = (unsigned int)(((int)bits) >> 31) | 0x80000000u;
            s_keys[base + j] = pres ? 0xFFFFFFFFu : (bits ^ msk);
            int d = __float2int_rd(qv[j] * 4096.0f);   // exact ×2^12, monotone
            digr[j] = min(NBINS - 1, max(0, d));
        }
    }
    ((int4*)s_hist)[tid] = make_int4(0, 0, 0, 0);       // zero histogram
    int ws = sum;
    #pragma unroll
    for (int o = 1; o < 32; o <<= 1) {
        int v = __shfl_up_sync(0xFFFFFFFFu, ws, o);
        if (lane >= o) ws += v;
    }
    if (lane == 31) s_wsum[warp] = ws;
    if (tid == 0) { s_scal[1] = -1; s_scal[4] = 0; }
    __syncthreads();                                    // B1

    if (warp == 0) {                                    // n_present total
        int v = s_wsum[lane];
        #pragma unroll
        for (int o = 16; o; o >>= 1) v += __shfl_down_sync(0xFFFFFFFFu, v, o);
        if (lane == 0) s_scal[0] = v;
    }
    #pragma unroll
    for (int j = 0; j < PT; j++)
        if (!presf[j]) atomicAdd(&s_hist[digr[j]], 1);  // uniform bins, low contention
    __syncthreads();                                    // B2

    const int n_present = s_scal[0];
    const int n_neg = K - n_present;

    // winner-bin search: block scan over 4096 bins
    int4 cc = ((int4*)s_hist)[tid];
    int cb[4] = {cc.x, cc.y, cc.z, cc.w};
    int tot = cb[0] + cb[1] + cb[2] + cb[3];
    int sc = tot;
    #pragma unroll
    for (int o = 1; o < 32; o <<= 1) {
        int v = __shfl_up_sync(0xFFFFFFFFu, sc, o);
        if (lane >= o) sc += v;
    }
    if (lane == 31) s_wsum[warp] = sc;
    __syncthreads();                                    // B3
    if (warp == 0) {
        int v = s_wsum[lane];
        int vs = v;
        #pragma unroll
        for (int o = 1; o < 32; o <<= 1) {
            int t2 = __shfl_up_sync(0xFFFFFFFFu, vs, o);
            if (lane >= o) vs += t2;
        }
        s_wsum[lane] = vs - v;
    }
    __syncthreads();                                    // B4
    if (n_neg > 0) {
        int cum = s_wsum[warp] + (sc - tot);
        #pragma unroll
        for (int j = 0; j < 4; j++) {
            if (cum < n_neg && n_neg <= cum + cb[j]) {
                s_scal[1] = tid * 4 + j;
                s_scal[2] = n_neg - cum;
                s_scal[3] = cb[j];
            }
            cum += cb[j];
        }
    }
    __syncthreads();                                    // B5
    const int winbin = s_scal[1];
    const int t_rem  = s_scal[2];
    const int cnt_eq = s_scal[3];
    const bool need_exact = (winbin >= 0) && (t_rem < cnt_eq);

    int* s_cand = s_hist;                               // reuse
    if (need_exact) {
        #pragma unroll
        for (int j = 0; j < PT; j++)
            if (!presf[j] && digr[j] == winbin)
                s_cand[atomicAdd(&s_scal[4], 1)] = base + j;
        __syncthreads();                                // B6 (uniform branch)
    }

    // keep decision + compaction scan -> packed idxmap
    int keep[PT];
    sum = 0;
    #pragma unroll
    for (int j = 0; j < PT; j++) {
        bool kp;
        if (presf[j]) kp = true;
        else if (winbin < 0) kp = false;
        else {
            int d = digr[j];
            if (d < winbin) kp = true;
            else if (d > winbin) kp = false;
            else if (!need_exact) kp = true;
            else {
                unsigned int my = s_keys[base + j];
                int myi = base + j, r = 0, nc = s_scal[4];
                for (int t = 0; t < nc; t++) {
                    int ci = s_cand[t];
                    unsigned int ck = s_keys[ci];
                    r += (ck < my) || (ck == my && ci < myi);
                }
                kp = (r < t_rem);                       // stable (key, idx) rank
            }
        }
        keep[j] = kp ? 1 : 0;
        local[j] = sum;
        sum += keep[j];
    }
    ws = sum;
    #pragma unroll
    for (int o = 1; o < 32; o <<= 1) {
        int v = __shfl_up_sync(0xFFFFFFFFu, ws, o);
        if (lane >= o) ws += v;
    }
    if (lane == 31) s_wsum[warp] = ws;
    __syncthreads();                                    // B7
    if (warp == 0) {
        int v = s_wsum[lane];
        int vs = v;
        #pragma unroll
        for (int o = 1; o < 32; o <<= 1) {
            int t2 = __shfl_up_sync(0xFFFFFFFFu, vs, o);
            if (lane >= o) vs += t2;
        }
        s_wsum[lane] = vs - v;
    }
    __syncthreads();                                    // B8
    {
        int tb = s_wsum[warp] + (ws - sum);
        #pragma unroll
        for (int j = 0; j < PT; j++)
            if (keep[j]) {
                int p = tb + local[j];
                if (p < KPAD) {
                    int e = (base + j) | (presf[j] << 15);
                    s_idxmap[p] = e;
                    g_idx[b * KPAD + p] = e;            // feed kernel B
                }
            }
    }
    __syncthreads();                                    // B9

    // ---- small epilogue: where / modified / depth (K < TPB: 1 iter) ----
    float* out_where = out;                             // [B, K, 4]
    float* out_mod   = out + (size_t)B * K * 4;         // [B, K, 1]
    float* out_depth = out + (size_t)B * K * 69;        // [B, K, 1]

    const float4* zw4 = (const float4*)z_where + (size_t)b * NSLOTS;
    const float*  zd  = z_depth_loc + (size_t)b * NSLOTS;

    for (int p = tid; p < K; p += TPB) {
        int e = s_idxmap[p];
        int slot = e & 0xFFF;
        bool pres = (e & 0x8000) != 0;
        float4 w = __ldg(&zw4[slot]);
        float m = fmaxf(w.z, w.w);
        ((float4*)out_where)[(size_t)b * K + p] = make_float4(w.x, w.y, m, m);
        out_mod[(size_t)b * K + p]   = pres ? 1.0f : -1.0f;
        out_depth[(size_t)b * K + p] = pres ? __ldg(&zd[slot]) : 0.0f;
    }
}

// =============== Kernel B: pure what-gather streamer ===============
__global__ __launch_bounds__(TPB_B) void what_kernel(
    const float* __restrict__ z_what_loc,
    float* __restrict__ out,
    int B, int K, int pc)
{
    __shared__ int s_e[128];

    const int b      = blockIdx.x;
    const int pstart = blockIdx.y * pc;
    const int n      = min(K, pstart + pc) - pstart;
    const int tid    = threadIdx.x;

    for (int t = tid; t < n; t += TPB_B)
        s_e[t] = g_idx[b * KPAD + pstart + t];
    __syncthreads();

    const float4* wl4 = (const float4*)z_what_loc + (size_t)b * NSLOTS * 16;
    float4* ow4 = (float4*)(out + (size_t)B * K * 5) + ((size_t)b * K + pstart) * 16;
    const int total = n * 16;
    const int c = tid & 15;                             // loop-invariant column
    int i = tid;
    for (; i + 3 * TPB_B < total; i += 4 * TPB_B) {
        int e0 = s_e[(i            ) >> 4];
        int e1 = s_e[(i +     TPB_B) >> 4];
        int e2 = s_e[(i + 2 * TPB_B) >> 4];
        int e3 = s_e[(i + 3 * TPB_B) >> 4];
        float4 v0 = make_float4(0.f, 0.f, 0.f, 0.f);
        float4 v1 = v0, v2 = v0, v3 = v0;
        if (e0 & 0x8000) v0 = __ldg(&wl4[(e0 & 0xFFF) * 16 + c]);
        if (e1 & 0x8000) v1 = __ldg(&wl4[(e1 & 0xFFF) * 16 + c]);
        if (e2 & 0x8000) v2 = __ldg(&wl4[(e2 & 0xFFF) * 16 + c]);
        if (e3 & 0x8000) v3 = __ldg(&wl4[(e3 & 0xFFF) * 16 + c]);
        ow4[i            ] = v0;
        ow4[i +     TPB_B] = v1;
        ow4[i + 2 * TPB_B] = v2;
        ow4[i + 3 * TPB_B] = v3;
    }
    for (; i < total; i += TPB_B) {
        int e = s_e[i >> 4];
        float4 v = make_float4(0.f, 0.f, 0.f, 0.f);
        if (e & 0x8000) v = __ldg(&wl4[(e & 0xFFF) * 16 + c]);
        ow4[i] = v;
    }
}

extern "C" void kernel_launch(void* const* d_in, const int* in_sizes, int n_in,
                              void* d_out, int out_size) {
    const float* z_where      = (const float*)d_in[0];
    const float* z_present    = (const float*)d_in[1];
    const float* z_what_loc   = (const float*)d_in[2];
    // d_in[3] = z_what_scale  (never read)
    const float* z_depth_loc  = (const float*)d_in[4];
    // d_in[5] = z_depth_scale (never read)
    const float* neg_priority = (const float*)d_in[6];

    const int B = in_sizes[6] / NSLOTS;
    const int K = out_size / (B * 70);
    const int pc = (K + NSLICE - 1) / NSLICE;

    select_kernel<<<B, TPB>>>(z_where, z_present, z_depth_loc, neg_priority,
                              (float*)d_out, B, K);
    what_kernel<<<dim3(B, NSLICE), TPB_B>>>(z_what_loc, (float*)d_out, B, K, pc);
}

// round 14
// speedup vs baseline: 1.1548x; 1.1400x over previous
#include <cuda_runtime.h>
#include <stdint.h>

#define NSLOTS 4096
#define TPB 1024
#define PT 4            // NSLOTS / TPB
#define NBINS 4096
#define KPAD 672
#define WHATROWS 256
#define EPSF 1e-3f

// dynamic smem layout (bytes)
#define OFF_WHERE   0                        // float4[4096]   65536
#define OFF_WHAT    65536                    // float4[256*16] 65536
#define OFF_DEPTH   131072                   // float[4096]    16384
#define OFF_KEYS    147456                   // uint[4096]     16384
#define OFF_HIST    163840                   // int[4096]      16384 (reused as cand list)
#define OFF_IDXMAP  180224                   // int[672]        2688
#define OFF_PLIST   182912                   // int[256]        1024
#define OFF_WSUM    183936                   // int[32]          128
#define OFF_SCAL    184064                   // int[8]            32
#define SMEM_BYTES  184096

__device__ __forceinline__ void cp_async16(void* smem_dst, const void* gmem_src) {
    unsigned saddr = (unsigned)__cvta_generic_to_shared(smem_dst);
    asm volatile("cp.async.cg.shared.global [%0], [%1], 16;\n"
                 :: "r"(saddr), "l"(gmem_src) : "memory");
}

__global__ __launch_bounds__(TPB) void latent_handler_kernel(
    const float* __restrict__ z_where,
    const float* __restrict__ z_present,
    const float* __restrict__ z_what_loc,
    const float* __restrict__ z_depth_loc,
    const float* __restrict__ neg_priority,
    float* __restrict__ out,
    int B, int K)
{
    extern __shared__ char smem[];
    float4*       s_where  = (float4*)(smem + OFF_WHERE);
    float4*       s_what4  = (float4*)(smem + OFF_WHAT);
    float*        s_depth  = (float*) (smem + OFF_DEPTH);
    unsigned int* s_keys   = (unsigned int*)(smem + OFF_KEYS);
    int*          s_hist   = (int*)   (smem + OFF_HIST);
    int*          s_idxmap = (int*)   (smem + OFF_IDXMAP);
    int*          s_plist  = (int*)   (smem + OFF_PLIST);
    int*          s_wsum   = (int*)   (smem + OFF_WSUM);
    int*          s_scal   = (int*)   (smem + OFF_SCAL);

    const int b    = blockIdx.x;
    const int tid  = threadIdx.x;
    const int lane = tid & 31;
    const int warp = tid >> 5;
    const int base = tid * PT;

    // ---- t=0: fire-and-forget prefetch of contiguous where/depth rows ----
    {
        const float4* zw4 = (const float4*)z_where + (size_t)b * NSLOTS;
        #pragma unroll
        for (int v = 0; v < 4; v++)
            cp_async16(&s_where[tid + v * TPB], &zw4[tid + v * TPB]);
        const float4* zd4 = (const float4*)(z_depth_loc + (size_t)b * NSLOTS);
        cp_async16(&((float4*)s_depth)[tid], &zd4[tid]);
    }

    // ---- load presence + priority, build keys/digits, presence scan ----
    int presf[PT], local[PT], digr[PT];
    int sum = 0;
    {
        float4 p = ((const float4*)(z_present    + (size_t)b * NSLOTS))[tid];
        float4 q = ((const float4*)(neg_priority + (size_t)b * NSLOTS))[tid];
        float pv[4] = {p.x, p.y, p.z, p.w};
        float qv[4] = {q.x, q.y, q.z, q.w};
        #pragma unroll
        for (int j = 0; j < PT; j++) {
            bool pres = pv[j] > EPSF;
            presf[j] = pres ? 1 : 0;
            local[j] = sum;
            sum += presf[j];
            unsigned int bits = __float_as_uint(qv[j]);
            unsigned int msk  = (unsigned int)(((int)bits) >> 31) | 0x80000000u;
            s_keys[base + j] = pres ? 0xFFFFFFFFu : (bits ^ msk);
            int d = __float2int_rd(qv[j] * 4096.0f);    // exact ×2^12, monotone
            digr[j] = min(NBINS - 1, max(0, d));
        }
    }
    ((int4*)s_hist)[tid] = make_int4(0, 0, 0, 0);       // zero histogram
    int ws = sum;
    #pragma unroll
    for (int o = 1; o < 32; o <<= 1) {
        int v = __shfl_up_sync(0xFFFFFFFFu, ws, o);
        if (lane >= o) ws += v;
    }
    if (lane == 31) s_wsum[warp] = ws;
    if (tid == 0) { s_scal[1] = -1; s_scal[4] = 0; }
    __syncthreads();                                    // B1
    if (warp == 0) {
        int v = s_wsum[lane];
        int vs = v;
        #pragma unroll
        for (int o = 1; o < 32; o <<= 1) {
            int t2 = __shfl_up_sync(0xFFFFFFFFu, vs, o);
            if (lane >= o) vs += t2;
        }
        s_wsum[lane] = vs - v;                          // exclusive warp bases
        if (lane == 31) s_scal[0] = vs;                 // n_present total
    }
    __syncthreads();                                    // B2

    const int n_present = s_scal[0];
    const int n_neg = K - n_present;
    int prank[PT];
    {
        int tb = s_wsum[warp] + (ws - sum);
        #pragma unroll
        for (int j = 0; j < PT; j++) {
            prank[j] = 0;
            if (presf[j]) {
                int r = tb + local[j];
                prank[j] = r;
                if (r < WHATROWS) s_plist[r] = base + j;
            } else {
                atomicAdd(&s_hist[digr[j]], 1);         // uniform bins, low contention
            }
        }
    }
    __syncthreads();                                    // B3: plist + hist done

    // ---- overlap: prefetch the only gathered reads (present what rows) ----
    const float4* wl4 = (const float4*)z_what_loc + (size_t)b * NSLOTS * 16;
    {
        int npre = min(n_present, WHATROWS);
        for (int i = tid; i < npre * 16; i += TPB)
            cp_async16(&s_what4[i], &wl4[s_plist[i >> 4] * 16 + (i & 15)]);
        asm volatile("cp.async.commit_group;\n" ::: "memory");
    }

    // ---- winner-bin search: block scan over 4096 bins ----
    int4 cc = ((int4*)s_hist)[tid];
    int cb[4] = {cc.x, cc.y, cc.z, cc.w};
    int tot = cb[0] + cb[1] + cb[2] + cb[3];
    int sc = tot;
    #pragma unroll
    for (int o = 1; o < 32; o <<= 1) {
        int v = __shfl_up_sync(0xFFFFFFFFu, sc, o);
        if (lane >= o) sc += v;
    }
    if (lane == 31) s_wsum[warp] = sc;
    __syncthreads();                                    // B4
    if (warp == 0) {
        int v = s_wsum[lane];
        int vs = v;
        #pragma unroll
        for (int o = 1; o < 32; o <<= 1) {
            int t2 = __shfl_up_sync(0xFFFFFFFFu, vs, o);
            if (lane >= o) vs += t2;
        }
        s_wsum[lane] = vs - v;
    }
    __syncthreads();                                    // B5
    if (n_neg > 0) {
        int cum = s_wsum[warp] + (sc - tot);
        #pragma unroll
        for (int j = 0; j < 4; j++) {
            if (cum < n_neg && n_neg <= cum + cb[j]) {
                s_scal[1] = tid * 4 + j;
                s_scal[2] = n_neg - cum;
                s_scal[3] = cb[j];
            }
            cum += cb[j];
        }
    }
    __syncthreads();                                    // B6
    const int winbin = s_scal[1];
    const int t_rem  = s_scal[2];
    const int cnt_eq = s_scal[3];
    const bool need_exact = (winbin >= 0) && (t_rem < cnt_eq);

    int* s_cand = s_hist;                               // reuse
    if (need_exact) {
        #pragma unroll
        for (int j = 0; j < PT; j++)
            if (!presf[j] && digr[j] == winbin)
                s_cand[atomicAdd(&s_scal[4], 1)] = base + j;
        __syncthreads();                                // B7 (uniform branch)
    }

    // ---- keep decision + compaction scan -> packed idxmap ----
    int keep[PT];
    sum = 0;
    #pragma unroll
    for (int j = 0; j < PT; j++) {
        bool kp;
        if (presf[j]) kp = true;
        else if (winbin < 0) kp = false;
        else {
            int d = digr[j];
            if (d < winbin) kp = true;
            else if (d > winbin) kp = false;
            else if (!need_exact) kp = true;
            else {
                unsigned int my = s_keys[base + j];
                int myi = base + j, r = 0, nc = s_scal[4];
                for (int t = 0; t < nc; t++) {
                    int ci = s_cand[t];
                    unsigned int ck = s_keys[ci];
                    r += (ck < my) || (ck == my && ci < myi);
                }
                kp = (r < t_rem);                       // stable (key, idx) rank
            }
        }
        keep[j] = kp ? 1 : 0;
        local[j] = sum;
        sum += keep[j];
    }
    ws = sum;
    #pragma unroll
    for (int o = 1; o < 32; o <<= 1) {
        int v = __shfl_up_sync(0xFFFFFFFFu, ws, o);
        if (lane >= o) ws += v;
    }
    if (lane == 31) s_wsum[warp] = ws;
    __syncthreads();                                    // B8
    if (warp == 0) {
        int v = s_wsum[lane];
        int vs = v;
        #pragma unroll
        for (int o = 1; o < 32; o <<= 1) {
            int t2 = __shfl_up_sync(0xFFFFFFFFu, vs, o);
            if (lane >= o) vs += t2;
        }
        s_wsum[lane] = vs - v;
    }
    __syncthreads();                                    // B9
    {
        int tb = s_wsum[warp] + (ws - sum);
        #pragma unroll
        for (int j = 0; j < PT; j++)
            if (keep[j]) {
                int p = tb + local[j];
                if (p < KPAD)
                    s_idxmap[p] = (base + j) | (presf[j] << 15) | (prank[j] << 16);
            }
    }
    asm volatile("cp.async.wait_group 0;\n" ::: "memory");
    __syncthreads();                                    // B10

    // ---- epilogue: everything from smem -> pure streaming stores ----
    float* out_where = out;                             // [B, K, 4]
    float* out_mod   = out + (size_t)B * K * 4;         // [B, K, 1]
    float* out_what  = out + (size_t)B * K * 5;         // [B, K, 64]
    float* out_depth = out + (size_t)B * K * 69;        // [B, K, 1]

    for (int p = tid; p < K; p += TPB) {                // K < TPB: 1 iteration
        int e = s_idxmap[p];
        int slot = e & 0xFFF;
        bool pres = (e & 0x8000) != 0;
        float4 w = s_where[slot];
        float m = fmaxf(w.z, w.w);
        ((float4*)out_where)[(size_t)b * K + p] = make_float4(w.x, w.y, m, m);
        out_mod[(size_t)b * K + p]   = pres ? 1.0f : -1.0f;
        out_depth[(size_t)b * K + p] = pres ? s_depth[slot] : 0.0f;
    }

    float4* ow4 = (float4*)out_what + (size_t)b * K * 16;
    const int total = K * 16;
    const int c = tid & 15;                             // loop-invariant column
    for (int i = tid; i < total; i += TPB) {
        int e = s_idxmap[i >> 4];
        float4 v = make_float4(0.f, 0.f, 0.f, 0.f);
        if (e & 0x8000) {
            int r = (e >> 16) & 0xFF;
            v = s_what4[r * 16 + c];
        }
        ow4[i] = v;
    }
}

extern "C" void kernel_launch(void* const* d_in, const int* in_sizes, int n_in,
                              void* d_out, int out_size) {
    const float* z_where      = (const float*)d_in[0];
    const float* z_present    = (const float*)d_in[1];
    const float* z_what_loc   = (const float*)d_in[2];
    // d_in[3] = z_what_scale  (never read)
    const float* z_depth_loc  = (const float*)d_in[4];
    // d_in[5] = z_depth_scale (never read)
    const float* neg_priority = (const float*)d_in[6];

    const int B = in_sizes[6] / NSLOTS;
    const int K = out_size / (B * 70);

    cudaFuncSetAttribute(latent_handler_kernel,
                         cudaFuncAttributeMaxDynamicSharedMemorySize, SMEM_BYTES);

    latent_handler_kernel<<<B, TPB, SMEM_BYTES>>>(z_where, z_present, z_what_loc,
                                                  z_depth_loc, neg_priority,
                                                  (float*)d_out, B, K);
}